// round 12
// baseline (speedup 1.0000x reference)
#include <cuda_runtime.h>
#include <cuda_bf16.h>
#include <cstdint>

// Problem constants (match reference)
#define N_NODES     100000
#define INPUT_DIM   10000
#define OUTPUT_DIM  128
#define NNZ_TOTAL   2000000
#define INV_KEEP    ((float)(1.0/0.9))

// Row-range partitioning: warp w exclusively owns rows [w*RPW, w*RPW+RPW).
// => no atomics, no output init pass; every output row written exactly once.
#define THREADS_PER_BLOCK 256
#define WARPS_PER_BLOCK   (THREADS_PER_BLOCK / 32)
#define NUM_BLOCKS        888                        // 6 CTAs/SM * 148 SMs, one wave
#define TOTAL_WARPS       (NUM_BLOCKS * WARPS_PER_BLOCK)   // 7104
#define RPW               15                         // rows per warp
#define NW_USED           ((N_NODES + RPW - 1) / RPW)      // 6667 active warps

// Packed per-nnz record: [63:32] = v bits (dropout applied),
//                        [31:14] = row (17 bits used), [13:0] = col (14 bits).
__device__ __align__(16) unsigned long long g_packed[NNZ_TOTAL];  // 16 MB scratch
__device__ int g_row_start[NW_USED + 1];   // first nnz index with row >= w*RPW

// ---------------------------------------------------------------------------
// Fused prep:
//   - per-block mask-dtype detection from the first 4 KB (independent loads,
//     L2-hit after the first block; warp 0 -> shared -> all warps)
//       int32 0/1 LE:    nonzero bytes only at offset%4==0
//       float32 0.0/1.0: nonzero bytes only at offsets {2,3} (00 00 80 3F)
//       uint8 0/1:       nonzero bytes at all offsets
//   - pack (dropout-applied v, row, col) into one uint64 per nnz
//   - scatter g_row_start[] from the sorted rows array
// ---------------------------------------------------------------------------
__global__ void __launch_bounds__(256)
prep_kernel(const float* __restrict__ values,
            const int*   __restrict__ rows,
            const int*   __restrict__ cols,
            const unsigned char* __restrict__ mask_raw) {
    __shared__ int s_mode;

    // --- block-local dtype detection (warp 0) ---
    if (threadIdx.x < 32) {
        const unsigned int lane = threadIdx.x;
        const uint32_t* m32 = reinterpret_cast<const uint32_t*>(mask_raw);
        int nz0 = 0, nz_rest = 0;
        #pragma unroll
        for (int k = 0; k < 32; ++k) {                // 1024 words = 4096 B
            uint32_t w = m32[k * 32 + lane];          // independent loads (MLP=32)
            if (w & 0x000000FFu) nz0++;
            if (w & 0xFFFFFF00u) nz_rest++;
        }
        #pragma unroll
        for (int off = 16; off > 0; off >>= 1) {
            nz0     += __shfl_xor_sync(0xFFFFFFFFu, nz0,     off);
            nz_rest += __shfl_xor_sync(0xFFFFFFFFu, nz_rest, off);
        }
        if (lane == 0) {
            int mode;
            if (nz_rest == 0)      mode = 1;   // int32
            else if (nz0 == 0)     mode = 2;   // float32
            else                   mode = 0;   // uint8 / bool
            s_mode = mode;
        }
    }
    __syncthreads();
    const int mode = s_mode;

    const int*   mask_i32 = reinterpret_cast<const int*>(mask_raw);
    const float* mask_f32 = reinterpret_cast<const float*>(mask_raw);

    const int tid    = blockIdx.x * blockDim.x + threadIdx.x;
    const int stride = gridDim.x * blockDim.x;

    for (int i = tid; i < NNZ_TOTAL; i += stride) {
        const int r = rows[i];

        // pack
        float v = values[i];
        bool keep;
        if (mode == 0)      keep = (mask_raw[i] != 0);
        else if (mode == 1) keep = (mask_i32[i] != 0);
        else                keep = (mask_f32[i] != 0.0f);
        v = keep ? v * INV_KEEP : 0.0f;
        uint32_t lo = ((uint32_t)r << 14) | (uint32_t)cols[i];
        g_packed[i] = ((unsigned long long)__float_as_uint(v) << 32) | lo;

        // row_start scatter: set row_start[w] = i for every warp boundary
        // w*RPW in (rows[i-1], rows[i]]  (rows sorted ascending)
        int wlo;
        if (i == 0) {
            wlo = 0;
        } else {
            const int rp = rows[i - 1];               // L1/L2 hit (neighbor)
            wlo = rp / RPW + 1;
        }
        const int whi = r / RPW;
        for (int w = wlo; w <= whi; ++w) g_row_start[w] = i;

        if (i == NNZ_TOTAL - 1) {
            for (int w = r / RPW + 1; w <= NW_USED; ++w)
                g_row_start[w] = NNZ_TOTAL;
        }
    }
}

// ---------------------------------------------------------------------------
// Main SpMM, row-partitioned + unroll-2. Warp w owns rows [w*RPW, w*RPW+RPW)
// exclusively; its nnz range is [row_start[w], row_start[w+1]). Lane l owns
// output columns [4l, 4l+4) (float4 acc). On every row change the finished
// row is written with a PLAIN float4 store of bias+acc (no atomics anywhere);
// empty rows in the owned range get a bare bias store.
// Per pair of nnz: two broadcast LDG.64 (packed) + two W LDG.128 issued
// back-to-back before any branch (MLP=2 on the gather), with the next packed
// pair prefetched one iteration ahead.
// ---------------------------------------------------------------------------
__global__ void __launch_bounds__(THREADS_PER_BLOCK, 6)
spmm_dropout_kernel(const float* __restrict__ weights,
                    const float* __restrict__ bias,
                    float*       __restrict__ out) {
    const int warp = (blockIdx.x * THREADS_PER_BLOCK + threadIdx.x) >> 5;
    if (warp >= NW_USED) return;
    const int lane = threadIdx.x & 31;

    const int r0 = warp * RPW;
    int r1 = r0 + RPW;
    if (r1 > N_NODES) r1 = N_NODES;

    const int start = g_row_start[warp];
    const int end   = g_row_start[warp + 1];

    const int c0 = lane * 4;
    const float4 b4 = *reinterpret_cast<const float4*>(bias + c0);

    if (start >= end) {                   // no nnz in range: bias-only rows
        for (int rr = r0; rr < r1; ++rr)
            *reinterpret_cast<float4*>(out + rr * OUTPUT_DIM + c0) = b4;
        return;
    }

    float4 acc = make_float4(0.f, 0.f, 0.f, 0.f);

    unsigned long long pf0 = __ldg(&g_packed[start]);
    unsigned long long pf1 = (start + 1 < end) ? __ldg(&g_packed[start + 1]) : 0ull;

    int cur_row = (int)((uint32_t)pf0 >> 14);
    // bias-only rows before the first nnz row
    for (int rr = r0; rr < cur_row; ++rr)
        *reinterpret_cast<float4*>(out + rr * OUTPUT_DIM + c0) = b4;

    int i = start;
    for (; i + 1 < end; i += 2) {
        const unsigned long long p0 = pf0, p1 = pf1;
        const uint32_t lo0 = (uint32_t)p0, lo1 = (uint32_t)p1;
        const float v0 = __uint_as_float((uint32_t)(p0 >> 32));
        const float v1 = __uint_as_float((uint32_t)(p1 >> 32));
        const int cA = (int)(lo0 & 0x3FFFu), rA = (int)(lo0 >> 14);
        const int cB = (int)(lo1 & 0x3FFFu), rB = (int)(lo1 >> 14);

        // Both W gathers in flight before any branch.
        const float4 w0 =
            *reinterpret_cast<const float4*>(weights + cA * OUTPUT_DIM + c0);
        const float4 w1 =
            *reinterpret_cast<const float4*>(weights + cB * OUTPUT_DIM + c0);

        // Prefetch next packed pair.
        if (i + 3 < end) {
            pf0 = __ldg(&g_packed[i + 2]);
            pf1 = __ldg(&g_packed[i + 3]);
        } else if (i + 2 < end) {
            pf0 = __ldg(&g_packed[i + 2]);
        }

        if (rA != cur_row) {
            *reinterpret_cast<float4*>(out + cur_row * OUTPUT_DIM + c0) =
                make_float4(acc.x + b4.x, acc.y + b4.y,
                            acc.z + b4.z, acc.w + b4.w);
            for (int rr = cur_row + 1; rr < rA; ++rr)      // empty rows (rare)
                *reinterpret_cast<float4*>(out + rr * OUTPUT_DIM + c0) = b4;
            acc = make_float4(0.f, 0.f, 0.f, 0.f);
            cur_row = rA;
        }
        acc.x += v0 * w0.x; acc.y += v0 * w0.y;
        acc.z += v0 * w0.z; acc.w += v0 * w0.w;

        if (rB != cur_row) {
            *reinterpret_cast<float4*>(out + cur_row * OUTPUT_DIM + c0) =
                make_float4(acc.x + b4.x, acc.y + b4.y,
                            acc.z + b4.z, acc.w + b4.w);
            for (int rr = cur_row + 1; rr < rB; ++rr)
                *reinterpret_cast<float4*>(out + rr * OUTPUT_DIM + c0) = b4;
            acc = make_float4(0.f, 0.f, 0.f, 0.f);
            cur_row = rB;
        }
        acc.x += v1 * w1.x; acc.y += v1 * w1.y;
        acc.z += v1 * w1.z; acc.w += v1 * w1.w;
    }

    if (i < end) {                        // odd tail element
        const unsigned long long p0 = pf0;
        const uint32_t lo0 = (uint32_t)p0;
        const float v0 = __uint_as_float((uint32_t)(p0 >> 32));
        const int cA = (int)(lo0 & 0x3FFFu), rA = (int)(lo0 >> 14);
        const float4 w0 =
            *reinterpret_cast<const float4*>(weights + cA * OUTPUT_DIM + c0);
        if (rA != cur_row) {
            *reinterpret_cast<float4*>(out + cur_row * OUTPUT_DIM + c0) =
                make_float4(acc.x + b4.x, acc.y + b4.y,
                            acc.z + b4.z, acc.w + b4.w);
            for (int rr = cur_row + 1; rr < rA; ++rr)
                *reinterpret_cast<float4*>(out + rr * OUTPUT_DIM + c0) = b4;
            acc = make_float4(0.f, 0.f, 0.f, 0.f);
            cur_row = rA;
        }
        acc.x += v0 * w0.x; acc.y += v0 * w0.y;
        acc.z += v0 * w0.z; acc.w += v0 * w0.w;
    }

    // Final flush + trailing bias-only rows in the owned range.
    *reinterpret_cast<float4*>(out + cur_row * OUTPUT_DIM + c0) =
        make_float4(acc.x + b4.x, acc.y + b4.y, acc.z + b4.z, acc.w + b4.w);
    for (int rr = cur_row + 1; rr < r1; ++rr)
        *reinterpret_cast<float4*>(out + rr * OUTPUT_DIM + c0) = b4;
}

// ---------------------------------------------------------------------------
// Harness entry point. Input order per metadata:
//   0: values    (float32, NNZ)
//   1: rows      (int32,   NNZ, sorted ascending)
//   2: cols      (int32,   NNZ)
//   3: keep_mask (bool -> on-device dtype detected at runtime, NNZ)
//   4: weights   (float32, INPUT_DIM*OUTPUT_DIM)
//   5: bias      (float32, OUTPUT_DIM)
// Output: float32 [N_NODES, OUTPUT_DIM]
// ---------------------------------------------------------------------------
extern "C" void kernel_launch(void* const* d_in, const int* in_sizes, int n_in,
                              void* d_out, int out_size) {
    const float*         values  = (const float*)d_in[0];
    const int*           rows    = (const int*)d_in[1];
    const int*           cols    = (const int*)d_in[2];
    const unsigned char* mask    = (const unsigned char*)d_in[3];
    const float*         weights = (const float*)d_in[4];
    const float*         bias    = (const float*)d_in[5];
    float*               out     = (float*)d_out;

    prep_kernel<<<1184, 256>>>(values, rows, cols, mask);
    spmm_dropout_kernel<<<NUM_BLOCKS, THREADS_PER_BLOCK>>>(weights, bias, out);
}

// round 14
// speedup vs baseline: 1.0265x; 1.0265x over previous
#include <cuda_runtime.h>
#include <cuda_bf16.h>
#include <cstdint>

// Problem constants (match reference)
#define N_NODES     100000
#define INPUT_DIM   10000
#define OUTPUT_DIM  128
#define NNZ_TOTAL   2000000
#define INV_KEEP    ((float)(1.0/0.9))

// nnz-partitioned spmm geometry (R10 proven): one warp per contiguous even
// chunk of packed records, 6 CTAs/SM * 148 SMs = one exact wave.
#define THREADS_PER_BLOCK 256
#define WARPS_PER_BLOCK   (THREADS_PER_BLOCK / 32)
#define NUM_BLOCKS        888
#define TOTAL_WARPS       (NUM_BLOCKS * WARPS_PER_BLOCK)   // 7104
#define CHUNK             282   // even => pair loop needs no tail peel

// Packed per-nnz record: [63:32] = v bits (dropout applied),
//                        [31:14] = row (17 bits used), [13:0] = col (14 bits).
__device__ __align__(16) unsigned long long g_packed[NNZ_TOTAL];  // 16 MB scratch

// ---------------------------------------------------------------------------
// Fused prep (single streaming pass, ~60 MB):
//   - block-local mask-dtype detection from the first 4 KB (warp 0 -> shared):
//       int32 0/1 LE:    nonzero bytes only at offset%4==0
//       float32 0.0/1.0: nonzero bytes only at offsets {2,3} (00 00 80 3F)
//       uint8 0/1:       nonzero bytes at all offsets
//   - pack (dropout-applied v, row, col) into one uint64 per nnz
//   - write bias to exactly the rows spmm will hit with atomics (chunk-
//     boundary rows) and to rows with zero nnz (gaps / prefix / suffix),
//     replacing the old full 51 MB output-init pass.
// ---------------------------------------------------------------------------
__global__ void __launch_bounds__(256)
prep_kernel(const float* __restrict__ values,
            const int*   __restrict__ rows,
            const int*   __restrict__ cols,
            const unsigned char* __restrict__ mask_raw,
            const float* __restrict__ bias,
            float*       __restrict__ out) {
    __shared__ int s_mode;
    __shared__ float4 s_bias[32];         // bias as 32 float4

    // --- block-local dtype detection (warp 0) + bias stage (warp 1) ---
    if (threadIdx.x < 32) {
        const unsigned int lane = threadIdx.x;
        const uint32_t* m32 = reinterpret_cast<const uint32_t*>(mask_raw);
        int nz0 = 0, nz_rest = 0;
        #pragma unroll
        for (int k = 0; k < 32; ++k) {                // 1024 words = 4096 B
            uint32_t w = m32[k * 32 + lane];          // independent loads
            if (w & 0x000000FFu) nz0++;
            if (w & 0xFFFFFF00u) nz_rest++;
        }
        #pragma unroll
        for (int off = 16; off > 0; off >>= 1) {
            nz0     += __shfl_xor_sync(0xFFFFFFFFu, nz0,     off);
            nz_rest += __shfl_xor_sync(0xFFFFFFFFu, nz_rest, off);
        }
        if (lane == 0) {
            int mode;
            if (nz_rest == 0)      mode = 1;   // int32
            else if (nz0 == 0)     mode = 2;   // float32
            else                   mode = 0;   // uint8 / bool
            s_mode = mode;
        }
    } else if (threadIdx.x < 64) {
        const int l = threadIdx.x - 32;
        s_bias[l] = reinterpret_cast<const float4*>(bias)[l];
    }
    __syncthreads();
    const int mode = s_mode;

    const int*   mask_i32 = reinterpret_cast<const int*>(mask_raw);
    const float* mask_f32 = reinterpret_cast<const float*>(mask_raw);

    const int tid    = blockIdx.x * blockDim.x + threadIdx.x;
    const int stride = gridDim.x * blockDim.x;

    for (int i = tid; i < NNZ_TOTAL; i += stride) {
        const int r = rows[i];

        // ---- pack ----
        float v = values[i];
        bool keep;
        if (mode == 0)      keep = (mask_raw[i] != 0);
        else if (mode == 1) keep = (mask_i32[i] != 0);
        else                keep = (mask_f32[i] != 0.0f);
        v = keep ? v * INV_KEEP : 0.0f;
        uint32_t lo = ((uint32_t)r << 14) | (uint32_t)cols[i];
        g_packed[i] = ((unsigned long long)__float_as_uint(v) << 32) | lo;

        // ---- bias pre-writes for atomic-target / empty rows ----
        // chunk boundary: rows[w*CHUNK] (first row of chunk w, atomic) and
        // rows[w*CHUNK - 1] (last row of chunk w-1, final-flush atomic).
        const bool is_boundary = (i % CHUNK) == 0;
        if (is_boundary) {
            float4* d = reinterpret_cast<float4*>(out + r * OUTPUT_DIM);
            #pragma unroll 8
            for (int j = 0; j < 32; ++j) d[j] = s_bias[j];
            if (i > 0) {
                const int rp = rows[i - 1];
                if (rp != r) {
                    float4* d2 = reinterpret_cast<float4*>(out + rp * OUTPUT_DIM);
                    #pragma unroll 8
                    for (int j = 0; j < 32; ++j) d2[j] = s_bias[j];
                }
            }
        }
        // empty rows in the gap (rows sorted; statistically ~none)
        if (i > 0) {
            const int rp = rows[i - 1];
            for (int rr = rp + 1; rr < r; ++rr) {
                float4* d = reinterpret_cast<float4*>(out + rr * OUTPUT_DIM);
                #pragma unroll 8
                for (int j = 0; j < 32; ++j) d[j] = s_bias[j];
            }
        } else {                                  // prefix rows before rows[0]
            for (int rr = 0; rr < r; ++rr) {
                float4* d = reinterpret_cast<float4*>(out + rr * OUTPUT_DIM);
                #pragma unroll 8
                for (int j = 0; j < 32; ++j) d[j] = s_bias[j];
            }
        }
        if (i == NNZ_TOTAL - 1) {                 // last nnz row (atomic) + suffix
            float4* d = reinterpret_cast<float4*>(out + r * OUTPUT_DIM);
            #pragma unroll 8
            for (int j = 0; j < 32; ++j) d[j] = s_bias[j];
            for (int rr = r + 1; rr < N_NODES; ++rr) {
                float4* d2 = reinterpret_cast<float4*>(out + rr * OUTPUT_DIM);
                #pragma unroll 8
                for (int j = 0; j < 32; ++j) d2[j] = s_bias[j];
            }
        }
    }
}

// ---------------------------------------------------------------------------
// Main SpMM (R10-proven), unroll-2. One warp per contiguous even-sized nnz
// chunk. Lane l owns output columns [4l, 4l+4) and accumulates a float4.
// Rows are sorted, so same-row nnz are contiguous:
//   - a row flushed on an INTERIOR row-change is wholly owned by this warp
//      -> plain float4 store of bias + acc (overwrites poison directly).
//   - the chunk's first and last rows may be shared with neighbor warps
//      -> atomicAdd(acc) onto the bias baseline pre-written by prep_kernel.
// Per pair of nnz: one broadcast LDG.128 (2 packed records) + two W LDG.128s
// issued back-to-back BEFORE the row-change branches (MLP=2 on the gather).
// ---------------------------------------------------------------------------
__global__ void __launch_bounds__(THREADS_PER_BLOCK, 6)
spmm_dropout_kernel(const float* __restrict__ weights,
                    const float* __restrict__ bias,
                    float*       __restrict__ out) {
    const int warp = (blockIdx.x * THREADS_PER_BLOCK + threadIdx.x) >> 5;
    const int lane = threadIdx.x & 31;

    int start = warp * CHUNK;                 // even
    if (start >= NNZ_TOTAL) return;
    int end = start + CHUNK;
    if (end > NNZ_TOTAL) end = NNZ_TOTAL;     // still even (NNZ even)

    const int c0 = lane * 4;
    const float4 b4 = *reinterpret_cast<const float4*>(bias + c0);

    const ulonglong2* packed2 = reinterpret_cast<const ulonglong2*>(g_packed);

    float4 acc = make_float4(0.f, 0.f, 0.f, 0.f);

    ulonglong2 pp = __ldg(&packed2[start >> 1]);
    int cur_row = (int)((uint32_t)pp.x >> 14);
    const int first_row = cur_row;

    for (int i = start; i < end; i += 2) {
        const unsigned long long p0 = pp.x, p1 = pp.y;
        const uint32_t lo0 = (uint32_t)p0, lo1 = (uint32_t)p1;
        const float v0 = __uint_as_float((uint32_t)(p0 >> 32));
        const float v1 = __uint_as_float((uint32_t)(p1 >> 32));
        const int cA = (int)(lo0 & 0x3FFFu), rA = (int)(lo0 >> 14);
        const int cB = (int)(lo1 & 0x3FFFu), rB = (int)(lo1 >> 14);

        // Issue both W gathers before any branch -> 2 loads in flight.
        const float4 w0 =
            *reinterpret_cast<const float4*>(weights + cA * OUTPUT_DIM + c0);
        const float4 w1 =
            *reinterpret_cast<const float4*>(weights + cB * OUTPUT_DIM + c0);

        // Prefetch the next packed pair.
        if (i + 2 < end) pp = __ldg(&packed2[(i + 2) >> 1]);

        if (rA != cur_row) {
            float* dst = out + cur_row * OUTPUT_DIM + c0;
            if (cur_row == first_row) {
                atomicAdd(dst + 0, acc.x); atomicAdd(dst + 1, acc.y);
                atomicAdd(dst + 2, acc.z); atomicAdd(dst + 3, acc.w);
            } else {
                *reinterpret_cast<float4*>(dst) =
                    make_float4(acc.x + b4.x, acc.y + b4.y,
                                acc.z + b4.z, acc.w + b4.w);
            }
            acc = make_float4(0.f, 0.f, 0.f, 0.f);
            cur_row = rA;
        }
        acc.x += v0 * w0.x; acc.y += v0 * w0.y;
        acc.z += v0 * w0.z; acc.w += v0 * w0.w;

        if (rB != cur_row) {
            float* dst = out + cur_row * OUTPUT_DIM + c0;
            if (cur_row == first_row) {
                atomicAdd(dst + 0, acc.x); atomicAdd(dst + 1, acc.y);
                atomicAdd(dst + 2, acc.z); atomicAdd(dst + 3, acc.w);
            } else {
                *reinterpret_cast<float4*>(dst) =
                    make_float4(acc.x + b4.x, acc.y + b4.y,
                                acc.z + b4.z, acc.w + b4.w);
            }
            acc = make_float4(0.f, 0.f, 0.f, 0.f);
            cur_row = rB;
        }
        acc.x += v1 * w1.x; acc.y += v1 * w1.y;
        acc.z += v1 * w1.z; acc.w += v1 * w1.w;
    }

    // Final flush: the chunk's last row may extend into the next warp's
    // chunk -> atomic onto the bias baseline pre-written by prep_kernel.
    {
        float* dst = out + cur_row * OUTPUT_DIM + c0;
        atomicAdd(dst + 0, acc.x); atomicAdd(dst + 1, acc.y);
        atomicAdd(dst + 2, acc.z); atomicAdd(dst + 3, acc.w);
    }
}

// ---------------------------------------------------------------------------
// Harness entry point. Input order per metadata:
//   0: values    (float32, NNZ)
//   1: rows      (int32,   NNZ, sorted ascending)
//   2: cols      (int32,   NNZ)
//   3: keep_mask (bool -> on-device dtype detected at runtime, NNZ)
//   4: weights   (float32, INPUT_DIM*OUTPUT_DIM)
//   5: bias      (float32, OUTPUT_DIM)
// Output: float32 [N_NODES, OUTPUT_DIM]
// ---------------------------------------------------------------------------
extern "C" void kernel_launch(void* const* d_in, const int* in_sizes, int n_in,
                              void* d_out, int out_size) {
    const float*         values  = (const float*)d_in[0];
    const int*           rows    = (const int*)d_in[1];
    const int*           cols    = (const int*)d_in[2];
    const unsigned char* mask    = (const unsigned char*)d_in[3];
    const float*         weights = (const float*)d_in[4];
    const float*         bias    = (const float*)d_in[5];
    float*               out     = (float*)d_out;

    prep_kernel<<<1184, 256>>>(values, rows, cols, mask, bias, out);
    spmm_dropout_kernel<<<NUM_BLOCKS, THREADS_PER_BLOCK>>>(weights, bias, out);
}

// round 17
// speedup vs baseline: 1.0858x; 1.0578x over previous
#include <cuda_runtime.h>
#include <cuda_fp16.h>
#include <cstdint>

// Problem constants (match reference)
#define N_NODES     100000
#define INPUT_DIM   10000
#define OUTPUT_DIM  128
#define NNZ_TOTAL   2000000
#define INV_KEEP    ((float)(1.0/0.9))

// nnz-partitioned spmm geometry: one warp per contiguous even chunk.
#define THREADS_PER_BLOCK 256
#define NUM_BLOCKS        888                        // 6 CTAs/SM * 148 SMs
#define TOTAL_WARPS       (NUM_BLOCKS * (THREADS_PER_BLOCK / 32))  // 7104
#define CHUNK             282                        // even => no pair-loop tail

// Prep geometry: 1954 pack blocks (4 nnz/thread, exact) + 625 W-convert blocks
#define PACK_BLOCKS   1954
#define WCONV_BLOCKS  625                            // 160000 threads * 8 elems
#define PREP_BLOCKS   (PACK_BLOCKS + WCONV_BLOCKS)

// Packed per-nnz record: [63:32] = v bits (dropout applied),
//                        [31:14] = row (17 bits), [13:0] = col (14 bits).
__device__ __align__(16) unsigned long long g_packed[NNZ_TOTAL];   // 16 MB
__device__ __align__(16) __half g_wh[INPUT_DIM * OUTPUT_DIM];      // 2.56 MB

struct alignas(8) half4 { __half2 a, b; };

// ---------------------------------------------------------------------------
// Write one full output row = bias (rare path: empty rows + atomic targets).
// ---------------------------------------------------------------------------
__device__ __forceinline__ void write_bias_row(float* __restrict__ out, int r,
                                               const float4* __restrict__ sb) {
    float4* d = reinterpret_cast<float4*>(out + r * OUTPUT_DIM);
    #pragma unroll 8
    for (int j = 0; j < 32; ++j) d[j] = sb[j];
}

// ---------------------------------------------------------------------------
// Fused prep.
//  Blocks [0, PACK_BLOCKS): pack 4 nnz/thread (vectorized), detect mask dtype
//    per block, and pre-write bias baselines for every row spmm touches with
//    atomics (chunk-boundary rows) plus empty/prefix/suffix rows.
//  Blocks [PACK_BLOCKS, PREP_BLOCKS): convert W fp32 -> fp16 (8 elems/thread).
// Mask dtype detection (first 4 KB):
//    int32 0/1 LE:    nonzero bytes only at offset%4==0
//    float32 0.0/1.0: nonzero bytes only at offsets {2,3} (00 00 80 3F)
//    uint8 0/1:       nonzero bytes at all offsets
// ---------------------------------------------------------------------------
__global__ void __launch_bounds__(256)
prep_kernel(const float* __restrict__ values,
            const int*   __restrict__ rows,
            const int*   __restrict__ cols,
            const unsigned char* __restrict__ mask_raw,
            const float* __restrict__ weights,
            const float* __restrict__ bias,
            float*       __restrict__ out) {
    // ---------------- W fp32 -> fp16 conversion blocks ----------------
    if (blockIdx.x >= PACK_BLOCKS) {
        const int t = (blockIdx.x - PACK_BLOCKS) * 256 + threadIdx.x; // < 160000
        const float4* w4 = reinterpret_cast<const float4*>(weights);
        const float4 a = w4[t * 2 + 0];
        const float4 b = w4[t * 2 + 1];
        uint4 o;
        __half2 h;
        h = __float22half2_rn(make_float2(a.x, a.y)); o.x = *reinterpret_cast<uint32_t*>(&h);
        h = __float22half2_rn(make_float2(a.z, a.w)); o.y = *reinterpret_cast<uint32_t*>(&h);
        h = __float22half2_rn(make_float2(b.x, b.y)); o.z = *reinterpret_cast<uint32_t*>(&h);
        h = __float22half2_rn(make_float2(b.z, b.w)); o.w = *reinterpret_cast<uint32_t*>(&h);
        reinterpret_cast<uint4*>(g_wh)[t] = o;
        return;
    }

    // ---------------- pack blocks ----------------
    __shared__ int s_mode;
    __shared__ float4 s_bias[32];

    if (threadIdx.x < 32) {
        const unsigned int lane = threadIdx.x;
        const uint32_t* m32 = reinterpret_cast<const uint32_t*>(mask_raw);
        int nz0 = 0, nz_rest = 0;
        #pragma unroll
        for (int k = 0; k < 32; ++k) {                 // 4096 B
            uint32_t w = m32[k * 32 + lane];
            if (w & 0x000000FFu) nz0++;
            if (w & 0xFFFFFF00u) nz_rest++;
        }
        #pragma unroll
        for (int off = 16; off > 0; off >>= 1) {
            nz0     += __shfl_xor_sync(0xFFFFFFFFu, nz0,     off);
            nz_rest += __shfl_xor_sync(0xFFFFFFFFu, nz_rest, off);
        }
        if (lane == 0) {
            int mode;
            if (nz_rest == 0)      mode = 1;   // int32
            else if (nz0 == 0)     mode = 2;   // float32
            else                   mode = 0;   // uint8 / bool
            s_mode = mode;
        }
    } else if (threadIdx.x < 64) {
        const int l = threadIdx.x - 32;
        s_bias[l] = reinterpret_cast<const float4*>(bias)[l];
    }
    __syncthreads();
    const int mode = s_mode;

    const int tid = blockIdx.x * 256 + threadIdx.x;    // quad index
    if (tid >= NNZ_TOTAL / 4) return;
    const int i0 = tid * 4;

    // vectorized loads
    const float4 v4 = *reinterpret_cast<const float4*>(values + i0);
    const int4   r4 = *reinterpret_cast<const int4*>(rows + i0);
    const int4   c4 = *reinterpret_cast<const int4*>(cols + i0);

    bool k0, k1, k2, k3;
    if (mode == 1) {
        const int4 m = *reinterpret_cast<const int4*>(
            reinterpret_cast<const int*>(mask_raw) + i0);
        k0 = m.x != 0; k1 = m.y != 0; k2 = m.z != 0; k3 = m.w != 0;
    } else if (mode == 2) {
        const float4 m = *reinterpret_cast<const float4*>(
            reinterpret_cast<const float*>(mask_raw) + i0);
        k0 = m.x != 0.f; k1 = m.y != 0.f; k2 = m.z != 0.f; k3 = m.w != 0.f;
    } else {
        const uint32_t m = *reinterpret_cast<const uint32_t*>(mask_raw + i0);
        k0 = (m & 0x000000FFu) != 0; k1 = (m & 0x0000FF00u) != 0;
        k2 = (m & 0x00FF0000u) != 0; k3 = (m & 0xFF000000u) != 0;
    }

    const float f0 = k0 ? v4.x * INV_KEEP : 0.f;
    const float f1 = k1 ? v4.y * INV_KEEP : 0.f;
    const float f2 = k2 ? v4.z * INV_KEEP : 0.f;
    const float f3 = k3 ? v4.w * INV_KEEP : 0.f;

    ulonglong2 o01, o23;
    o01.x = ((unsigned long long)__float_as_uint(f0) << 32) |
            (((uint32_t)r4.x << 14) | (uint32_t)c4.x);
    o01.y = ((unsigned long long)__float_as_uint(f1) << 32) |
            (((uint32_t)r4.y << 14) | (uint32_t)c4.y);
    o23.x = ((unsigned long long)__float_as_uint(f2) << 32) |
            (((uint32_t)r4.z << 14) | (uint32_t)c4.z);
    o23.y = ((unsigned long long)__float_as_uint(f3) << 32) |
            (((uint32_t)r4.w << 14) | (uint32_t)c4.w);
    reinterpret_cast<ulonglong2*>(g_packed)[tid * 2 + 0] = o01;
    reinterpret_cast<ulonglong2*>(g_packed)[tid * 2 + 1] = o23;

    // ---- bias baselines ----
    // chunk boundaries in [i0, i0+3]: atomics target rows[i] and rows[i-1]
    {
        const int rm = i0 % CHUNK;
        const int rr[4] = {r4.x, r4.y, r4.z, r4.w};
        #pragma unroll
        for (int j = 0; j < 4; ++j) {
            if (((rm + j) % CHUNK) == 0) {
                const int i = i0 + j;
                write_bias_row(out, rr[j], s_bias);
                if (i > 0) {
                    const int rp = (j > 0) ? rr[j - 1] : __ldg(rows + i - 1);
                    if (rp != rr[j]) write_bias_row(out, rp, s_bias);
                }
            }
        }
    }
    // empty rows in gaps (sorted rows; statistically ~none)
    {
        const int rp = (i0 == 0) ? -1 : __ldg(rows + i0 - 1);
        const int prevs[4] = {(i0 == 0) ? 0 : rp + 1, r4.x + 1, r4.y + 1, r4.z + 1};
        const int currs[4] = {r4.x, r4.y, r4.z, r4.w};
        #pragma unroll
        for (int j = 0; j < 4; ++j)
            for (int rr2 = prevs[j]; rr2 < currs[j]; ++rr2)
                write_bias_row(out, rr2, s_bias);
    }
    // last quad: last-row atomic target + suffix rows
    if (i0 + 4 == NNZ_TOTAL) {
        write_bias_row(out, r4.w, s_bias);
        for (int rr2 = r4.w + 1; rr2 < N_NODES; ++rr2)
            write_bias_row(out, rr2, s_bias);
    }
}

// ---------------------------------------------------------------------------
// Main SpMM, unroll-2, fp16 W. One warp per contiguous even-sized nnz chunk.
// Lane l owns output columns [4l, 4l+4) (float4 acc, fp32 accumulation).
// Sorted rows => same-row nnz contiguous:
//   - INTERIOR row-change: row wholly owned -> plain float4 store of
//     bias + acc (overwrites poison directly).
//   - chunk's first/last rows may be shared -> atomicAdd onto the bias
//     baseline pre-written by prep_kernel.
// Per pair of nnz: one broadcast LDG.128 (2 packed records) + two W LDG.64s
// (fp16, 256 B/warp each = 2 wavefronts) issued before any branch.
// ---------------------------------------------------------------------------
__global__ void __launch_bounds__(THREADS_PER_BLOCK, 6)
spmm_dropout_kernel(const float* __restrict__ bias,
                    float*       __restrict__ out) {
    const int warp = (blockIdx.x * THREADS_PER_BLOCK + threadIdx.x) >> 5;
    const int lane = threadIdx.x & 31;

    int start = warp * CHUNK;                 // even
    if (start >= NNZ_TOTAL) return;
    int end = start + CHUNK;
    if (end > NNZ_TOTAL) end = NNZ_TOTAL;     // still even

    const int c0 = lane * 4;
    const float4 b4 = *reinterpret_cast<const float4*>(bias + c0);
    const __half* __restrict__ wh = g_wh;

    const ulonglong2* packed2 = reinterpret_cast<const ulonglong2*>(g_packed);

    float4 acc = make_float4(0.f, 0.f, 0.f, 0.f);

    ulonglong2 pp = __ldg(&packed2[start >> 1]);
    int cur_row = (int)((uint32_t)pp.x >> 14);
    const int first_row = cur_row;

    for (int i = start; i < end; i += 2) {
        const unsigned long long p0 = pp.x, p1 = pp.y;
        const uint32_t lo0 = (uint32_t)p0, lo1 = (uint32_t)p1;
        const float v0 = __uint_as_float((uint32_t)(p0 >> 32));
        const float v1 = __uint_as_float((uint32_t)(p1 >> 32));
        const int cA = (int)(lo0 & 0x3FFFu), rA = (int)(lo0 >> 14);
        const int cB = (int)(lo1 & 0x3FFFu), rB = (int)(lo1 >> 14);

        // Both fp16 W gathers in flight before any branch (LDG.64 each).
        const half4 wA = *reinterpret_cast<const half4*>(wh + cA * OUTPUT_DIM + c0);
        const half4 wB = *reinterpret_cast<const half4*>(wh + cB * OUTPUT_DIM + c0);

        // Prefetch the next packed pair.
        if (i + 2 < end) pp = __ldg(&packed2[(i + 2) >> 1]);

        const float2 a01 = __half22float2(wA.a), a23 = __half22float2(wA.b);
        const float2 b01 = __half22float2(wB.a), b23 = __half22float2(wB.b);

        if (rA != cur_row) {
            float* dst = out + cur_row * OUTPUT_DIM + c0;
            if (cur_row == first_row) {
                atomicAdd(dst + 0, acc.x); atomicAdd(dst + 1, acc.y);
                atomicAdd(dst + 2, acc.z); atomicAdd(dst + 3, acc.w);
            } else {
                *reinterpret_cast<float4*>(dst) =
                    make_float4(acc.x + b4.x, acc.y + b4.y,
                                acc.z + b4.z, acc.w + b4.w);
            }
            acc = make_float4(0.f, 0.f, 0.f, 0.f);
            cur_row = rA;
        }
        acc.x += v0 * a01.x; acc.y += v0 * a01.y;
        acc.z += v0 * a23.x; acc.w += v0 * a23.y;

        if (rB != cur_row) {
            float* dst = out + cur_row * OUTPUT_DIM + c0;
            if (cur_row == first_row) {
                atomicAdd(dst + 0, acc.x); atomicAdd(dst + 1, acc.y);
                atomicAdd(dst + 2, acc.z); atomicAdd(dst + 3, acc.w);
            } else {
                *reinterpret_cast<float4*>(dst) =
                    make_float4(acc.x + b4.x, acc.y + b4.y,
                                acc.z + b4.z, acc.w + b4.w);
            }
            acc = make_float4(0.f, 0.f, 0.f, 0.f);
            cur_row = rB;
        }
        acc.x += v1 * b01.x; acc.y += v1 * b01.y;
        acc.z += v1 * b23.x; acc.w += v1 * b23.y;
    }

    // Final flush: last row may extend into the next warp's chunk -> atomic
    // onto the bias baseline pre-written by prep_kernel.
    {
        float* dst = out + cur_row * OUTPUT_DIM + c0;
        atomicAdd(dst + 0, acc.x); atomicAdd(dst + 1, acc.y);
        atomicAdd(dst + 2, acc.z); atomicAdd(dst + 3, acc.w);
    }
}

// ---------------------------------------------------------------------------
// Harness entry point. Input order per metadata:
//   0: values    (float32, NNZ)
//   1: rows      (int32,   NNZ, sorted ascending)
//   2: cols      (int32,   NNZ)
//   3: keep_mask (bool -> on-device dtype detected at runtime, NNZ)
//   4: weights   (float32, INPUT_DIM*OUTPUT_DIM)
//   5: bias      (float32, OUTPUT_DIM)
// Output: float32 [N_NODES, OUTPUT_DIM]
// ---------------------------------------------------------------------------
extern "C" void kernel_launch(void* const* d_in, const int* in_sizes, int n_in,
                              void* d_out, int out_size) {
    const float*         values  = (const float*)d_in[0];
    const int*           rows    = (const int*)d_in[1];
    const int*           cols    = (const int*)d_in[2];
    const unsigned char* mask    = (const unsigned char*)d_in[3];
    const float*         weights = (const float*)d_in[4];
    const float*         bias    = (const float*)d_in[5];
    float*               out     = (float*)d_out;

    prep_kernel<<<PREP_BLOCKS, 256>>>(values, rows, cols, mask,
                                      weights, bias, out);
    spmm_dropout_kernel<<<NUM_BLOCKS, THREADS_PER_BLOCK>>>(bias, out);
}